// round 7
// baseline (speedup 1.0000x reference)
#include <cuda_runtime.h>
#include <cuda_fp16.h>
#include <stdint.h>

// Problem constants (fixed shapes)
#define NB 2
#define NN 20000
#define NF 256
#define NE 640000
#define KDIM 512
#define MO 256
#define MTOT (NB*NN)        // 40000 GEMM rows
#define NDEG_PAD 20480      // padded node count for vector ops

// ---------------- device scratch ----------------
__device__ int   g_flag;
__device__ __align__(16) int g_deg4[NDEG_PAD * 4];   // per-node 4-replica histogram
__device__ __align__(16) int g_cur4[NDEG_PAD * 4];   // absolute per-replica cursors
__device__ __align__(16) int g_off[NDEG_PAD];        // [NN+1] node starts
__device__ int   g_src[NE];
// A matrix [MTOT][512] fp16. cols 0..255 = agg, 256..511 = fp16 copy of x
__device__ __align__(16) __half g_A[(size_t)MTOT * KDIM];
// W concat [256][512] fp16: k<256 from W_l, else W_r
__device__ __align__(16) __half g_W[(size_t)MO * KDIM];

// ---------------- PTX helpers (base sm_103-safe only) ----------------
__device__ __forceinline__ uint32_t smem_u32(const void* p) {
    return (uint32_t)__cvta_generic_to_shared(p);
}
#define CP_ASYNC16(s, g) \
    asm volatile("cp.async.cg.shared.global [%0], [%1], 16;" :: "r"(s), "l"(g))
#define CP_COMMIT() asm volatile("cp.async.commit_group;" ::: "memory")
#define CP_WAIT0()  asm volatile("cp.async.wait_group 0;" ::: "memory")

__device__ __forceinline__ void ldmx4(uint32_t& r0, uint32_t& r1, uint32_t& r2, uint32_t& r3,
                                      uint32_t addr) {
    asm volatile("ldmatrix.sync.aligned.m8n8.x4.shared.b16 {%0,%1,%2,%3}, [%4];"
                 : "=r"(r0), "=r"(r1), "=r"(r2), "=r"(r3) : "r"(addr));
}
__device__ __forceinline__ void mma16816(float* c, const uint32_t* a, const uint32_t* b) {
    asm volatile(
        "mma.sync.aligned.m16n8k16.row.col.f32.f16.f16.f32 "
        "{%0,%1,%2,%3}, {%4,%5,%6,%7}, {%8,%9}, {%0,%1,%2,%3};"
        : "+f"(c[0]), "+f"(c[1]), "+f"(c[2]), "+f"(c[3])
        : "r"(a[0]), "r"(a[1]), "r"(a[2]), "r"(a[3]), "r"(b[0]), "r"(b[1]));
}

// ---------------- setup: detect dtype + zero histogram ----------------
__global__ void zero_kernel(const void* ei) {
    int i = blockIdx.x * blockDim.x + threadIdx.x;
    if (i == 0) {
        const int2* p = (const int2*)ei;
        int is64 = 1;
        for (int q = 0; q < 64; q++)
            if (p[q].y != 0) { is64 = 0; break; }
        g_flag = is64;
    }
    if (i < NDEG_PAD) ((int4*)g_deg4)[i] = make_int4(0, 0, 0, 0);
}

// load 4 consecutive indices, dtype-adaptive, vectorized
__device__ __forceinline__ void load_idx4(const void* ei, long long base, int* o) {
    if (g_flag) {
        const longlong2* p = (const longlong2*)((const long long*)ei + base);
        longlong2 a = p[0], b = p[1];
        o[0] = (int)a.x; o[1] = (int)a.y; o[2] = (int)b.x; o[3] = (int)b.y;
    } else {
        int4 a = *(const int4*)((const int*)ei + base);
        o[0] = a.x; o[1] = a.y; o[2] = a.z; o[3] = a.w;
    }
}

__global__ void count_kernel(const void* __restrict__ ei, int E) {
    int e = (blockIdx.x * blockDim.x + threadIdx.x) * 4;
    if (e + 4 <= E) {
        int t[4];
        load_idx4(ei, (long long)E + e, t);
#pragma unroll
        for (int j = 0; j < 4; j++) atomicAdd(&g_deg4[t[j] * 4 + j], 1);
    } else {
        for (int j = 0; e + j < E; j++) {
            int t = g_flag ? (int)((const long long*)ei)[(long long)E + e + j]
                           : ((const int*)ei)[E + e + j];
            atomicAdd(&g_deg4[t * 4 + ((e + j) & 3)], 1);
        }
    }
}

// single-block scan over per-node totals; writes g_off (node starts, int4-vectorized)
// and g_cur4 (absolute per-replica bases).
__global__ void scan_kernel() {
    __shared__ int warp_sums[32];
    const int CH = 20;
    int t = threadIdx.x;
    int lane = t & 31, w = t >> 5;
    int base = t * CH;
    int v[CH];
    {
        int s = 0;
#pragma unroll
        for (int i = 0; i < CH; i++) {
            int4 d = ((const int4*)g_deg4)[base + i];
            s += d.x + d.y + d.z + d.w;
            v[i] = s;
        }
    }
    int s = v[CH - 1];
    int x = s;
#pragma unroll
    for (int off = 1; off < 32; off *= 2) {
        int y = __shfl_up_sync(0xffffffffu, x, off);
        if (lane >= off) x += y;
    }
    if (lane == 31) warp_sums[w] = x;
    __syncthreads();
    if (w == 0) {
        int ws = warp_sums[lane];
#pragma unroll
        for (int off = 1; off < 32; off *= 2) {
            int y = __shfl_up_sync(0xffffffffu, ws, off);
            if (lane >= off) ws += y;
        }
        warp_sums[lane] = ws;
    }
    __syncthreads();
    int thrExcl = ((w > 0) ? warp_sums[w - 1] : 0) + (x - s);
    int arr[CH];
    arr[0] = thrExcl;
#pragma unroll
    for (int i = 1; i < CH; i++) arr[i] = thrExcl + v[i - 1];
#pragma unroll
    for (int q = 0; q < 5; q++)
        ((int4*)g_off)[t * 5 + q] = *(const int4*)&arr[q * 4];
#pragma unroll
    for (int i = 0; i < CH; i++) {
        int4 d = ((const int4*)g_deg4)[base + i];
        int e0 = arr[i];
        int4 c;
        c.x = e0;
        c.y = e0 + d.x;
        c.z = e0 + d.x + d.y;
        c.w = e0 + d.x + d.y + d.z;
        ((int4*)g_cur4)[base + i] = c;
    }
}

__global__ void fill_kernel(const void* __restrict__ ei, int E) {
    int e = (blockIdx.x * blockDim.x + threadIdx.x) * 4;
    if (e + 4 <= E) {
        int t[4], s[4];
        load_idx4(ei, (long long)E + e, t);
        load_idx4(ei, (long long)e, s);
        int p0 = atomicAdd(&g_cur4[t[0] * 4 + 0], 1);
        int p1 = atomicAdd(&g_cur4[t[1] * 4 + 1], 1);
        int p2 = atomicAdd(&g_cur4[t[2] * 4 + 2], 1);
        int p3 = atomicAdd(&g_cur4[t[3] * 4 + 3], 1);
        g_src[p0] = s[0];
        g_src[p1] = s[1];
        g_src[p2] = s[2];
        g_src[p3] = s[3];
    } else {
        for (int j = 0; e + j < E; j++) {
            int t = g_flag ? (int)((const long long*)ei)[(long long)E + e + j]
                           : ((const int*)ei)[E + e + j];
            int s = g_flag ? (int)((const long long*)ei)[e + j]
                           : ((const int*)ei)[e + j];
            int pos = atomicAdd(&g_cur4[t * 4 + ((e + j) & 3)], 1);
            g_src[pos] = s;
        }
    }
}

// ---------------- x -> fp16 A cols [256,512) ; W -> fp16 (merged) ----------------
#define XCONV_TOT (MTOT * (NF / 8))
__global__ void conv_kernel(const float* __restrict__ x,
                            const float* __restrict__ Wl,
                            const float* __restrict__ Wr) {
    int idx = blockIdx.x * blockDim.x + threadIdx.x;
    if (idx < XCONV_TOT) {
        int m = idx >> 5;                  // 32 chunks of 8 per row
        int fq = (idx & 31) * 8;
        float4 v0 = ((const float4*)x)[idx * 2];
        float4 v1 = ((const float4*)x)[idx * 2 + 1];
        union { __half h[8]; uint4 u; } o;
        o.h[0] = __float2half_rn(v0.x); o.h[1] = __float2half_rn(v0.y);
        o.h[2] = __float2half_rn(v0.z); o.h[3] = __float2half_rn(v0.w);
        o.h[4] = __float2half_rn(v1.x); o.h[5] = __float2half_rn(v1.y);
        o.h[6] = __float2half_rn(v1.z); o.h[7] = __float2half_rn(v1.w);
        *(uint4*)&g_A[(size_t)m * KDIM + 256 + fq] = o.u;
    }
    if (idx < MO * KDIM / 8) {             // W: 8 floats per thread
        int o = idx >> 6, k = (idx & 63) * 8;
        const float* src = (k < NF) ? (Wl + o * NF + k) : (Wr + o * NF + (k - NF));
        float4 a = *(const float4*)src;
        float4 b = *(const float4*)(src + 4);
        union { __half h[8]; uint4 u; } w;
        w.h[0] = __float2half_rn(a.x); w.h[1] = __float2half_rn(a.y);
        w.h[2] = __float2half_rn(a.z); w.h[3] = __float2half_rn(a.w);
        w.h[4] = __float2half_rn(b.x); w.h[5] = __float2half_rn(b.y);
        w.h[6] = __float2half_rn(b.z); w.h[7] = __float2half_rn(b.w);
        *(uint4*)&g_W[o * KDIM + k] = w.u;
    }
}

// ---------------- mean aggregation: fp16 gather from g_A x-columns ----------------
__device__ __forceinline__ void acc8(float* acc, uint4 v) {
    const __half2* h = (const __half2*)&v;
#pragma unroll
    for (int q = 0; q < 4; q++) {
        float2 f = __half22float2(h[q]);
        acc[2 * q]     += f.x;
        acc[2 * q + 1] += f.y;
    }
}

__global__ __launch_bounds__(64)
void agg_kernel() {
    int node = blockIdx.x;
    int t = threadIdx.x;
    int batch = t >> 5, lane = t & 31;
    int s0 = g_off[node], s1 = g_off[node + 1];
    __shared__ int sSrc[64];
    const uint4* __restrict__ xb = (const uint4*)g_A;  // 64 uint4 per row
    size_t bbase = (size_t)batch * NN;
    float acc[8] = {0.f, 0.f, 0.f, 0.f, 0.f, 0.f, 0.f, 0.f};

    for (int base = s0; base < s1; base += 64) {
        int cnt = min(64, s1 - base);
        if (t < cnt) sSrc[t] = g_src[base + t];
        __syncthreads();
        int i = 0;
        for (; i + 4 <= cnt; i += 4) {
            uint4 v0 = xb[(bbase + sSrc[i + 0]) * 64 + 32 + lane];
            uint4 v1 = xb[(bbase + sSrc[i + 1]) * 64 + 32 + lane];
            uint4 v2 = xb[(bbase + sSrc[i + 2]) * 64 + 32 + lane];
            uint4 v3 = xb[(bbase + sSrc[i + 3]) * 64 + 32 + lane];
            acc8(acc, v0); acc8(acc, v1); acc8(acc, v2); acc8(acc, v3);
        }
        for (; i < cnt; i++) {
            uint4 v = xb[(bbase + sSrc[i]) * 64 + 32 + lane];
            acc8(acc, v);
        }
        __syncthreads();
    }

    float inv = 1.0f / fmaxf((float)(s1 - s0), 1.0f);
    union { __half h[8]; uint4 u; } hv;
#pragma unroll
    for (int j = 0; j < 8; j++) hv.h[j] = __float2half_rn(acc[j] * inv);
    *(uint4*)&g_A[(bbase + node) * (size_t)KDIM + lane * 8] = hv.u;
}

// ---------------- mma.sync GEMM (single fp16 pass, K=512) ----------------
#define BM 128
#define BN 128
#define BK 32
#define NIT 16
#define SKW 40   // halves per smem row (32 + 8 pad)

__global__ __launch_bounds__(256, 2)
void mma_gemm_kernel(const float* __restrict__ bl, float* __restrict__ out) {
    __shared__ __align__(16) __half As[2][BM * SKW];
    __shared__ __align__(16) __half Bs[2][BN * SKW];
    __shared__ float s_bias[BN];

    int tid = threadIdx.x;
    int lane = tid & 31, wid = tid >> 5;
    int bm = blockIdx.x * BM;
    int bn = blockIdx.y * BN;
    int wm = (wid & 3) * 32;     // warp tile 32x64
    int wn = (wid >> 2) * 64;

    if (tid < BN) s_bias[tid] = bl[bn + tid];

    uint32_t sA[2] = { smem_u32(&As[0][0]), smem_u32(&As[1][0]) };
    uint32_t sB[2] = { smem_u32(&Bs[0][0]), smem_u32(&Bs[1][0]) };

    float acc[2][8][4];
#pragma unroll
    for (int i = 0; i < 2; i++)
#pragma unroll
        for (int j = 0; j < 8; j++)
#pragma unroll
            for (int q = 0; q < 4; q++) acc[i][j][q] = 0.f;

    auto load_tiles = [&](int it, int buf) {
        int k0 = it << 5;
#pragma unroll
        for (int i = 0; i < 2; i++) {
            int c = tid + i * 256;       // 512 16B-chunks per tile
            int row = c >> 2, q = c & 3;
            int m = bm + row; if (m >= MTOT) m = MTOT - 1;
            CP_ASYNC16(sA[buf] + (row * SKW + q * 8) * 2,
                       g_A + (size_t)m * KDIM + k0 + q * 8);
            int n = bn + row;
            CP_ASYNC16(sB[buf] + (row * SKW + q * 8) * 2,
                       g_W + (size_t)n * KDIM + k0 + q * 8);
        }
        CP_COMMIT();
    };

    load_tiles(0, 0);
    int buf = 0;

    for (int it = 0; it < NIT; it++) {
        CP_WAIT0();
        __syncthreads();
        if (it + 1 < NIT) load_tiles(it + 1, buf ^ 1);

#pragma unroll
        for (int kk = 0; kk < 2; kk++) {
            uint32_t a[2][4], b[8][2];
#pragma unroll
            for (int mt = 0; mt < 2; mt++) {
                uint32_t addr = sA[buf] +
                    ((wm + mt * 16 + (lane & 15)) * SKW + kk * 16 + (lane >> 4) * 8) * 2;
                ldmx4(a[mt][0], a[mt][1], a[mt][2], a[mt][3], addr);
            }
#pragma unroll
            for (int np = 0; np < 4; np++) {
                int rowB = wn + np * 16 + (lane & 7) + ((lane >> 4) << 3);
                uint32_t addr = sB[buf] +
                    (rowB * SKW + kk * 16 + ((lane >> 3) & 1) * 8) * 2;
                ldmx4(b[2 * np][0], b[2 * np][1], b[2 * np + 1][0], b[2 * np + 1][1], addr);
            }
#pragma unroll
            for (int mt = 0; mt < 2; mt++)
#pragma unroll
                for (int nt = 0; nt < 8; nt++)
                    mma16816(acc[mt][nt], a[mt], b[nt]);
        }
        __syncthreads();
        buf ^= 1;
    }

    // epilogue: bias + relu, float2 stores
    int g = lane >> 2, t4 = lane & 3;
#pragma unroll
    for (int mt = 0; mt < 2; mt++) {
#pragma unroll
        for (int nt = 0; nt < 8; nt++) {
            int o = bn + wn + nt * 8 + t4 * 2;
            float b0 = s_bias[wn + nt * 8 + t4 * 2];
            float b1 = s_bias[wn + nt * 8 + t4 * 2 + 1];
            int m0 = bm + wm + mt * 16 + g;
            if (m0 < MTOT) {
                float2 v;
                v.x = fmaxf(acc[mt][nt][0] + b0, 0.f);
                v.y = fmaxf(acc[mt][nt][1] + b1, 0.f);
                *(float2*)(out + (size_t)m0 * MO + o) = v;
            }
            int m1 = m0 + 8;
            if (m1 < MTOT) {
                float2 v;
                v.x = fmaxf(acc[mt][nt][2] + b0, 0.f);
                v.y = fmaxf(acc[mt][nt][3] + b1, 0.f);
                *(float2*)(out + (size_t)m1 * MO + o) = v;
            }
        }
    }
}

// ---------------- launch ----------------
extern "C" void kernel_launch(void* const* d_in, const int* in_sizes, int n_in,
                              void* d_out, int out_size) {
    const float* x  = (const float*)d_in[0];
    const void*  ei = d_in[1];
    const float* Wl = (const float*)d_in[2];
    const float* bl = (const float*)d_in[3];
    const float* Wr = (const float*)d_in[4];
    float* out = (float*)d_out;
    int E = in_sizes[1] / 2;

    static cudaStream_t s1 = nullptr;
    static cudaEvent_t evFork = nullptr, evJoin = nullptr;
    if (!s1) {
        cudaStreamCreateWithFlags(&s1, cudaStreamNonBlocking);
        cudaEventCreateWithFlags(&evFork, cudaEventDisableTiming);
        cudaEventCreateWithFlags(&evJoin, cudaEventDisableTiming);
    }

    zero_kernel<<<(NDEG_PAD + 255) / 256, 256>>>(ei);

    // fork: conv (independent of graph setup) runs on side stream
    cudaEventRecord(evFork, 0);
    cudaStreamWaitEvent(s1, evFork, 0);
    conv_kernel<<<(XCONV_TOT + 255) / 256, 256, 0, s1>>>(x, Wl, Wr);
    cudaEventRecord(evJoin, s1);

    count_kernel<<<(E / 4 + 255) / 256, 256>>>(ei, E);
    scan_kernel<<<1, 1024>>>();
    fill_kernel<<<(E / 4 + 255) / 256, 256>>>(ei, E);

    // join before agg (needs conv's x-columns)
    cudaStreamWaitEvent(0, evJoin, 0);
    agg_kernel<<<NN, 64>>>();
    dim3 ggrid((MTOT + BM - 1) / BM, MO / BN);
    mma_gemm_kernel<<<ggrid, 256>>>(bl, out);
}

// round 8
// speedup vs baseline: 1.2600x; 1.2600x over previous
#include <cuda_runtime.h>
#include <cuda_fp16.h>
#include <stdint.h>

// Problem constants (fixed shapes)
#define NB 2
#define NN 20000
#define NF 256
#define NE 640000
#define KDIM 512
#define MO 256
#define MTOT (NB*NN)        // 40000 GEMM rows
#define NDEG_PAD 20480      // padded node count (multiple of 1024)
#define NBLK 20             // NDEG_PAD / 1024

// ---------------- device scratch ----------------
__device__ int   g_flag;
__device__ __align__(16) int g_deg4[NDEG_PAD * 4];   // per-node 4-replica histogram
__device__ __align__(16) int g_cur4[NDEG_PAD * 4];   // absolute per-replica cursors
__device__ __align__(16) int g_off[NDEG_PAD];        // [NN+1] node starts
__device__ int   g_incl[NDEG_PAD];                   // per-node inclusive sum within block
__device__ int   g_blk[NBLK];                        // per-block totals
__device__ int   g_src[NE];
// A matrix [MTOT][512] fp16. cols 0..255 = agg, 256..511 = fp16 copy of x
__device__ __align__(16) __half g_A[(size_t)MTOT * KDIM];
// W concat [256][512] fp16: k<256 from W_l, else W_r
__device__ __align__(16) __half g_W[(size_t)MO * KDIM];

// ---------------- PTX helpers (base sm_103-safe only) ----------------
__device__ __forceinline__ uint32_t smem_u32(const void* p) {
    return (uint32_t)__cvta_generic_to_shared(p);
}
#define CP_ASYNC16(s, g) \
    asm volatile("cp.async.cg.shared.global [%0], [%1], 16;" :: "r"(s), "l"(g))
#define CP_COMMIT() asm volatile("cp.async.commit_group;" ::: "memory")
#define CP_WAIT0()  asm volatile("cp.async.wait_group 0;" ::: "memory")

__device__ __forceinline__ void ldmx4(uint32_t& r0, uint32_t& r1, uint32_t& r2, uint32_t& r3,
                                      uint32_t addr) {
    asm volatile("ldmatrix.sync.aligned.m8n8.x4.shared.b16 {%0,%1,%2,%3}, [%4];"
                 : "=r"(r0), "=r"(r1), "=r"(r2), "=r"(r3) : "r"(addr));
}
__device__ __forceinline__ void mma16816(float* c, const uint32_t* a, const uint32_t* b) {
    asm volatile(
        "mma.sync.aligned.m16n8k16.row.col.f32.f16.f16.f32 "
        "{%0,%1,%2,%3}, {%4,%5,%6,%7}, {%8,%9}, {%0,%1,%2,%3};"
        : "+f"(c[0]), "+f"(c[1]), "+f"(c[2]), "+f"(c[3])
        : "r"(a[0]), "r"(a[1]), "r"(a[2]), "r"(a[3]), "r"(b[0]), "r"(b[1]));
}

// ---------------- setup: detect dtype + zero histogram ----------------
__global__ void zero_kernel(const void* ei) {
    int i = blockIdx.x * blockDim.x + threadIdx.x;
    if (i == 0) {
        const int2* p = (const int2*)ei;
        int is64 = 1;
        for (int q = 0; q < 64; q++)
            if (p[q].y != 0) { is64 = 0; break; }
        g_flag = is64;
    }
    if (i < NDEG_PAD) ((int4*)g_deg4)[i] = make_int4(0, 0, 0, 0);
}

// load 4 consecutive indices, dtype-adaptive, vectorized
__device__ __forceinline__ void load_idx4(const void* ei, long long base, int* o) {
    if (g_flag) {
        const longlong2* p = (const longlong2*)((const long long*)ei + base);
        longlong2 a = p[0], b = p[1];
        o[0] = (int)a.x; o[1] = (int)a.y; o[2] = (int)b.x; o[3] = (int)b.y;
    } else {
        int4 a = *(const int4*)((const int*)ei + base);
        o[0] = a.x; o[1] = a.y; o[2] = a.z; o[3] = a.w;
    }
}

__global__ void count_kernel(const void* __restrict__ ei, int E) {
    int e = (blockIdx.x * blockDim.x + threadIdx.x) * 4;
    if (e + 4 <= E) {
        int t[4];
        load_idx4(ei, (long long)E + e, t);
#pragma unroll
        for (int j = 0; j < 4; j++) atomicAdd(&g_deg4[t[j] * 4 + j], 1);
    } else {
        for (int j = 0; e + j < E; j++) {
            int t = g_flag ? (int)((const long long*)ei)[(long long)E + e + j]
                           : ((const int*)ei)[E + e + j];
            atomicAdd(&g_deg4[t * 4 + ((e + j) & 3)], 1);
        }
    }
}

// scan phase 1: 20 blocks x 1024; block-local inclusive scan of per-node totals
__global__ void scan1_kernel() {
    __shared__ int warp_sums[32];
    int n = blockIdx.x * 1024 + threadIdx.x;
    int lane = threadIdx.x & 31, w = threadIdx.x >> 5;
    int4 d = ((const int4*)g_deg4)[n];
    int v = d.x + d.y + d.z + d.w;
    int x = v;
#pragma unroll
    for (int off = 1; off < 32; off *= 2) {
        int y = __shfl_up_sync(0xffffffffu, x, off);
        if (lane >= off) x += y;
    }
    if (lane == 31) warp_sums[w] = x;
    __syncthreads();
    if (w == 0) {
        int ws = warp_sums[lane];
#pragma unroll
        for (int off = 1; off < 32; off *= 2) {
            int y = __shfl_up_sync(0xffffffffu, ws, off);
            if (lane >= off) ws += y;
        }
        warp_sums[lane] = ws;
    }
    __syncthreads();
    int incl = x + ((w > 0) ? warp_sums[w - 1] : 0);
    g_incl[n] = incl;
    if (threadIdx.x == 1023) g_blk[blockIdx.x] = incl;
}

// scan phase 2: per node, add block offset; write g_off and absolute cursors
__global__ void scan2_kernel() {
    int n = blockIdx.x * blockDim.x + threadIdx.x;
    if (n >= NDEG_PAD) return;
    int b = n >> 10;
    int blkoff = 0;
    for (int j = 0; j < b; j++) blkoff += g_blk[j];
    int4 d = ((const int4*)g_deg4)[n];
    int tot = d.x + d.y + d.z + d.w;
    int excl = blkoff + g_incl[n] - tot;
    g_off[n] = excl;
    int4 c;
    c.x = excl;
    c.y = excl + d.x;
    c.z = excl + d.x + d.y;
    c.w = excl + d.x + d.y + d.z;
    ((int4*)g_cur4)[n] = c;
}

__global__ void fill_kernel(const void* __restrict__ ei, int E) {
    int e = (blockIdx.x * blockDim.x + threadIdx.x) * 4;
    if (e + 4 <= E) {
        int t[4], s[4];
        load_idx4(ei, (long long)E + e, t);
        load_idx4(ei, (long long)e, s);
        int p0 = atomicAdd(&g_cur4[t[0] * 4 + 0], 1);
        int p1 = atomicAdd(&g_cur4[t[1] * 4 + 1], 1);
        int p2 = atomicAdd(&g_cur4[t[2] * 4 + 2], 1);
        int p3 = atomicAdd(&g_cur4[t[3] * 4 + 3], 1);
        g_src[p0] = s[0];
        g_src[p1] = s[1];
        g_src[p2] = s[2];
        g_src[p3] = s[3];
    } else {
        for (int j = 0; e + j < E; j++) {
            int t = g_flag ? (int)((const long long*)ei)[(long long)E + e + j]
                           : ((const int*)ei)[E + e + j];
            int s = g_flag ? (int)((const long long*)ei)[e + j]
                           : ((const int*)ei)[e + j];
            int pos = atomicAdd(&g_cur4[t * 4 + ((e + j) & 3)], 1);
            g_src[pos] = s;
        }
    }
}

// ---------------- x -> fp16 A cols [256,512) ; W -> fp16 (merged) ----------------
#define XCONV_TOT (MTOT * (NF / 8))
__global__ void conv_kernel(const float* __restrict__ x,
                            const float* __restrict__ Wl,
                            const float* __restrict__ Wr) {
    int idx = blockIdx.x * blockDim.x + threadIdx.x;
    if (idx < XCONV_TOT) {
        int m = idx >> 5;                  // 32 chunks of 8 per row
        int fq = (idx & 31) * 8;
        float4 v0 = ((const float4*)x)[idx * 2];
        float4 v1 = ((const float4*)x)[idx * 2 + 1];
        union { __half h[8]; uint4 u; } o;
        o.h[0] = __float2half_rn(v0.x); o.h[1] = __float2half_rn(v0.y);
        o.h[2] = __float2half_rn(v0.z); o.h[3] = __float2half_rn(v0.w);
        o.h[4] = __float2half_rn(v1.x); o.h[5] = __float2half_rn(v1.y);
        o.h[6] = __float2half_rn(v1.z); o.h[7] = __float2half_rn(v1.w);
        *(uint4*)&g_A[(size_t)m * KDIM + 256 + fq] = o.u;
    }
    if (idx < MO * KDIM / 8) {             // W: 8 floats per thread
        int o = idx >> 6, k = (idx & 63) * 8;
        const float* src = (k < NF) ? (Wl + o * NF + k) : (Wr + o * NF + (k - NF));
        float4 a = *(const float4*)src;
        float4 b = *(const float4*)(src + 4);
        union { __half h[8]; uint4 u; } w;
        w.h[0] = __float2half_rn(a.x); w.h[1] = __float2half_rn(a.y);
        w.h[2] = __float2half_rn(a.z); w.h[3] = __float2half_rn(a.w);
        w.h[4] = __float2half_rn(b.x); w.h[5] = __float2half_rn(b.y);
        w.h[6] = __float2half_rn(b.z); w.h[7] = __float2half_rn(b.w);
        *(uint4*)&g_W[o * KDIM + k] = w.u;
    }
}

// ---------------- mean aggregation: fp16 gather from g_A x-columns ----------------
__device__ __forceinline__ void acc8(float* acc, uint4 v) {
    const __half2* h = (const __half2*)&v;
#pragma unroll
    for (int q = 0; q < 4; q++) {
        float2 f = __half22float2(h[q]);
        acc[2 * q]     += f.x;
        acc[2 * q + 1] += f.y;
    }
}

__global__ __launch_bounds__(64)
void agg_kernel() {
    int node = blockIdx.x;
    int t = threadIdx.x;
    int batch = t >> 5, lane = t & 31;
    int s0 = g_off[node], s1 = g_off[node + 1];
    __shared__ int sSrc[64];
    const uint4* __restrict__ xb = (const uint4*)g_A;  // 64 uint4 per row
    size_t bbase = (size_t)batch * NN;
    float acc[8] = {0.f, 0.f, 0.f, 0.f, 0.f, 0.f, 0.f, 0.f};

    for (int base = s0; base < s1; base += 64) {
        int cnt = min(64, s1 - base);
        if (t < cnt) sSrc[t] = g_src[base + t];
        __syncthreads();
        int i = 0;
        for (; i + 4 <= cnt; i += 4) {
            uint4 v0 = xb[(bbase + sSrc[i + 0]) * 64 + 32 + lane];
            uint4 v1 = xb[(bbase + sSrc[i + 1]) * 64 + 32 + lane];
            uint4 v2 = xb[(bbase + sSrc[i + 2]) * 64 + 32 + lane];
            uint4 v3 = xb[(bbase + sSrc[i + 3]) * 64 + 32 + lane];
            acc8(acc, v0); acc8(acc, v1); acc8(acc, v2); acc8(acc, v3);
        }
        for (; i < cnt; i++) {
            uint4 v = xb[(bbase + sSrc[i]) * 64 + 32 + lane];
            acc8(acc, v);
        }
        __syncthreads();
    }

    float inv = 1.0f / fmaxf((float)(s1 - s0), 1.0f);
    union { __half h[8]; uint4 u; } hv;
#pragma unroll
    for (int j = 0; j < 8; j++) hv.h[j] = __float2half_rn(acc[j] * inv);
    *(uint4*)&g_A[(bbase + node) * (size_t)KDIM + lane * 8] = hv.u;
}

// ---------------- mma.sync GEMM (single fp16 pass, K=512) ----------------
#define BM 128
#define BN 128
#define BK 32
#define NIT 16
#define SKW 40   // halves per smem row (32 + 8 pad)

__global__ __launch_bounds__(256, 2)
void mma_gemm_kernel(const float* __restrict__ bl, float* __restrict__ out) {
    __shared__ __align__(16) __half As[2][BM * SKW];
    __shared__ __align__(16) __half Bs[2][BN * SKW];
    __shared__ float s_bias[BN];

    int tid = threadIdx.x;
    int lane = tid & 31, wid = tid >> 5;
    int bm = blockIdx.x * BM;
    int bn = blockIdx.y * BN;
    int wm = (wid & 3) * 32;     // warp tile 32x64
    int wn = (wid >> 2) * 64;

    if (tid < BN) s_bias[tid] = bl[bn + tid];

    uint32_t sA[2] = { smem_u32(&As[0][0]), smem_u32(&As[1][0]) };
    uint32_t sB[2] = { smem_u32(&Bs[0][0]), smem_u32(&Bs[1][0]) };

    float acc[2][8][4];
#pragma unroll
    for (int i = 0; i < 2; i++)
#pragma unroll
        for (int j = 0; j < 8; j++)
#pragma unroll
            for (int q = 0; q < 4; q++) acc[i][j][q] = 0.f;

    auto load_tiles = [&](int it, int buf) {
        int k0 = it << 5;
#pragma unroll
        for (int i = 0; i < 2; i++) {
            int c = tid + i * 256;       // 512 16B-chunks per tile
            int row = c >> 2, q = c & 3;
            int m = bm + row; if (m >= MTOT) m = MTOT - 1;
            CP_ASYNC16(sA[buf] + (row * SKW + q * 8) * 2,
                       g_A + (size_t)m * KDIM + k0 + q * 8);
            int n = bn + row;
            CP_ASYNC16(sB[buf] + (row * SKW + q * 8) * 2,
                       g_W + (size_t)n * KDIM + k0 + q * 8);
        }
        CP_COMMIT();
    };

    load_tiles(0, 0);
    int buf = 0;

    for (int it = 0; it < NIT; it++) {
        CP_WAIT0();
        __syncthreads();
        if (it + 1 < NIT) load_tiles(it + 1, buf ^ 1);

#pragma unroll
        for (int kk = 0; kk < 2; kk++) {
            uint32_t a[2][4], b[8][2];
#pragma unroll
            for (int mt = 0; mt < 2; mt++) {
                uint32_t addr = sA[buf] +
                    ((wm + mt * 16 + (lane & 15)) * SKW + kk * 16 + (lane >> 4) * 8) * 2;
                ldmx4(a[mt][0], a[mt][1], a[mt][2], a[mt][3], addr);
            }
#pragma unroll
            for (int np = 0; np < 4; np++) {
                int rowB = wn + np * 16 + (lane & 7) + ((lane >> 4) << 3);
                uint32_t addr = sB[buf] +
                    (rowB * SKW + kk * 16 + ((lane >> 3) & 1) * 8) * 2;
                ldmx4(b[2 * np][0], b[2 * np][1], b[2 * np + 1][0], b[2 * np + 1][1], addr);
            }
#pragma unroll
            for (int mt = 0; mt < 2; mt++)
#pragma unroll
                for (int nt = 0; nt < 8; nt++)
                    mma16816(acc[mt][nt], a[mt], b[nt]);
        }
        __syncthreads();
        buf ^= 1;
    }

    // epilogue: bias + relu, float2 stores
    int g = lane >> 2, t4 = lane & 3;
#pragma unroll
    for (int mt = 0; mt < 2; mt++) {
#pragma unroll
        for (int nt = 0; nt < 8; nt++) {
            int o = bn + wn + nt * 8 + t4 * 2;
            float b0 = s_bias[wn + nt * 8 + t4 * 2];
            float b1 = s_bias[wn + nt * 8 + t4 * 2 + 1];
            int m0 = bm + wm + mt * 16 + g;
            if (m0 < MTOT) {
                float2 v;
                v.x = fmaxf(acc[mt][nt][0] + b0, 0.f);
                v.y = fmaxf(acc[mt][nt][1] + b1, 0.f);
                *(float2*)(out + (size_t)m0 * MO + o) = v;
            }
            int m1 = m0 + 8;
            if (m1 < MTOT) {
                float2 v;
                v.x = fmaxf(acc[mt][nt][2] + b0, 0.f);
                v.y = fmaxf(acc[mt][nt][3] + b1, 0.f);
                *(float2*)(out + (size_t)m1 * MO + o) = v;
            }
        }
    }
}

// ---------------- launch ----------------
extern "C" void kernel_launch(void* const* d_in, const int* in_sizes, int n_in,
                              void* d_out, int out_size) {
    const float* x  = (const float*)d_in[0];
    const void*  ei = d_in[1];
    const float* Wl = (const float*)d_in[2];
    const float* bl = (const float*)d_in[3];
    const float* Wr = (const float*)d_in[4];
    float* out = (float*)d_out;
    int E = in_sizes[1] / 2;

    static cudaStream_t s1 = nullptr;
    static cudaEvent_t evFork = nullptr, evJoin = nullptr;
    if (!s1) {
        cudaStreamCreateWithFlags(&s1, cudaStreamNonBlocking);
        cudaEventCreateWithFlags(&evFork, cudaEventDisableTiming);
        cudaEventCreateWithFlags(&evJoin, cudaEventDisableTiming);
    }

    zero_kernel<<<(NDEG_PAD + 255) / 256, 256>>>(ei);

    // fork: conv (independent of graph setup) runs on side stream
    cudaEventRecord(evFork, 0);
    cudaStreamWaitEvent(s1, evFork, 0);
    conv_kernel<<<(XCONV_TOT + 255) / 256, 256, 0, s1>>>(x, Wl, Wr);
    cudaEventRecord(evJoin, s1);

    count_kernel<<<(E / 4 + 255) / 256, 256>>>(ei, E);
    scan1_kernel<<<NBLK, 1024>>>();
    scan2_kernel<<<NDEG_PAD / 256, 256>>>();
    fill_kernel<<<(E / 4 + 255) / 256, 256>>>(ei, E);

    // join before agg (needs conv's x-columns)
    cudaStreamWaitEvent(0, evJoin, 0);
    agg_kernel<<<NN, 64>>>();
    dim3 ggrid((MTOT + BM - 1) / BM, MO / BN);
    mma_gemm_kernel<<<ggrid, 256>>>(bl, out);
}